// round 15
// baseline (speedup 1.0000x reference)
#include <cuda_runtime.h>
#include <cuda_fp16.h>

// Problem constants (fixed by the reference)
#define B_  2
#define C_  4
#define K_  32
#define H_  96
#define W_  96
#define D_  64
#define NV  (D_*D_*D_)          // 262144 voxels per batch
#define HWK (H_*W_*K_)

// Transposed, confidence-scaled heatmaps in fp16: [b,c,h,w,k] (4.7 MB)
__device__ __half g_hmT[B_ * C_ * HWK];

__device__ __forceinline__ float frcp_approx(float x) {
    float r; asm("rcp.approx.f32 %0, %1;" : "=f"(r) : "f"(x)); return r;
}
__device__ __forceinline__ __half2 u2h(unsigned v) {
    __half2 h; *(unsigned*)&h = v; return h;
}

// ---------------------------------------------------------------------------
// Kernel 1 (R9-proven): transpose (B,C,K,H,W) -> fp16 (B,C,H,W,K), folding
// normalized conf. grid (W/32, H/8, B*C), block (32,32). Stages 8 h-rows,
// single barrier, coalesced half2 stores.
// ---------------------------------------------------------------------------
__global__ void vt_transpose_kernel(const float* __restrict__ hm,
                                    const float* __restrict__ conf) {
    __shared__ float tile[8][32][33];
    __shared__ float sCn[32];
    const int bc = blockIdx.z;            // b*C + c
    const int b  = bc >> 2;
    const int w0 = blockIdx.x * 32;
    const int h0 = blockIdx.y * 8;
    const int tx = threadIdx.x, ty = threadIdx.y;
    const int tid = ty * 32 + tx;

    if (ty == 0) {
        const int k = tx;
        float s = 0.f;
        #pragma unroll
        for (int cc = 0; cc < C_; cc++) s += conf[(b * C_ + cc) * K_ + k];
        sCn[k] = conf[bc * K_ + k] / s;
    }
    __syncthreads();

    const float cn = sCn[ty];             // k = ty on the read side
    #pragma unroll
    for (int hh = 0; hh < 8; hh++)
        tile[hh][ty][tx] =
            hm[((bc * K_ + ty) * H_ + h0 + hh) * W_ + w0 + tx] * cn;
    __syncthreads();

    __half2* outT = (__half2*)g_hmT;
    #pragma unroll
    for (int i = 0; i < 4; i++) {
        const int idx = tid + i * 1024;
        const int h       = idx >> 9;         // 0..7
        const int w_local = (idx >> 4) & 31;  // 0..31
        const int k2      = idx & 15;         // half2 index 0..15
        outT[(((bc * H_ + h0 + h) * W_ + w0 + w_local) * K_) / 2 + k2] =
            __floats2half2_rn(tile[h][2 * k2 + 0][w_local],
                              tile[h][2 * k2 + 1][w_local]);
    }
}

// ---------------------------------------------------------------------------
// Kernel 2: pair-gather unprojection. Block = 256 threads = 32 voxels.
// Phase 1: one thread per (voxel, cam, y-row): computes the row's pair-load
//          base column xb (covers x0 and x1 in one contiguous 128B region)
//          and the two column weights, packed as uint2{ idx*4, h(wl)|h(wh)<<16 }.
// Phase 2: 8 threads/voxel. Per camera per y-row: ONE LDG.128 covers both
//          x-corners (half s<4 = column xb, half s>=4 = xb+1). HFMA2 combine,
//          fp32 flush per camera pair, shfl_xor(4) partner reduction at end.
// ---------------------------------------------------------------------------
__global__ __launch_bounds__(256, 6) void vt_unproject_kernel(
    const float* __restrict__ P,       // (B,C,3,4)
    const float* __restrict__ coords,  // (B,D,D,D,3)
    float* __restrict__ out)           // (B,K,D,D,D)
{
    const int tid = threadIdx.x;
    const int b   = blockIdx.x >> 13;            // NV/32 = 8192 blocks/batch
    const int nb  = (blockIdx.x & 8191) * 32;    // base voxel within batch

    __shared__ float sP[C_ * 12];
    __shared__ float sCrd[32 * 3];
    __shared__ uint2 sPack[256];   // [vox][cam][row] -> (idx*4, wl|wh<<16)
    __shared__ float tile[32][33];

    if (tid < C_ * 12) sP[tid] = P[b * C_ * 12 + tid];
    if (tid < 96)      sCrd[tid] = coords[(b * NV + nb) * 3 + tid];
    __syncthreads();

    // ---------------- Phase 1: one (voxel, cam, y-row) per thread ----------
    {
        const int vox = tid >> 3;
        const int cam = (tid >> 1) & 3;
        const int r   = tid & 1;
        const float x = sCrd[vox * 3 + 0];
        const float y = sCrd[vox * 3 + 1];
        const float z = sCrd[vox * 3 + 2];
        const float* p = &sP[cam * 12];

        const float pz = fmaf(p[8], x, fmaf(p[9], y, fmaf(p[10], z, p[11])));
        const bool zok = (pz > 0.f);

        const float s  = frcp_approx(pz) * (95.0f / 96.0f);
        const float un = fmaf(p[0], x, fmaf(p[1], y, fmaf(p[2], z, p[3])));
        const float vn = fmaf(p[4], x, fmaf(p[5], y, fmaf(p[6], z, p[7])));
        const float ix = un * s;
        const float iy = vn * s;

        const float x0f = floorf(ix), y0f = floorf(iy);
        const float wx1 = ix - x0f,  wx0 = 1.f - wx1;
        const float wy1 = iy - y0f,  wy0 = 1.f - wy1;

        // this thread's y row
        const float yrf = y0f + (float)r;
        const bool  byok = zok & (yrf >= 0.f) & (yrf <= 95.f);
        const float wyv  = byok ? (r ? wy1 : wy0) : 0.f;

        const bool bx0 = (x0f >= 0.f) & (x0f <= 95.f);
        const bool bx1 = (x0f >= -1.f) & (x0f <= 94.f);   // x1 = x0+1 in range
        const float wx0v = bx0 ? wx0 : 0.f;
        const float wx1v = bx1 ? wx1 : 0.f;

        const int x0i = (int)x0f;                  // exact (x0f is integral)
        const int xb  = min(max(x0i, 0), 94);      // pair base column

        // column xb weight / column xb+1 weight
        float wl = (xb == x0i) ? wx0v : ((xb == x0i + 1) ? wx1v : 0.f);
        float wh = (xb == x0i) ? wx1v : ((xb + 1 == x0i) ? wx0v : 0.f);
        wl *= wyv;
        wh *= wyv;

        const int yri = min(max((int)yrf, 0), 95);
        const unsigned idx4 = (unsigned)(yri * 96 + xb) * 4u;

        const __half hl = __float2half_rn(wl);
        const __half hh = __float2half_rn(wh);
        const unsigned w2 = (unsigned)*(const unsigned short*)&hl |
                            ((unsigned)*(const unsigned short*)&hh << 16);

        sPack[tid] = make_uint2(idx4, w2);   // tid == vox*8 + cam*2 + r
    }
    __syncthreads();

    // ---------------- Phase 2: pair gather (8 threads per voxel) -----------
    const int s8   = tid & 7;          // lane within voxel group
    const int vloc = tid >> 3;         // voxel within block
    const unsigned sel = (s8 & 4) ? 0x3232u : 0x1010u;  // hi/lo weight splat

    float acc0 = 0.f, acc1 = 0.f, acc2 = 0.f, acc3 = 0.f;
    float acc4 = 0.f, acc5 = 0.f, acc6 = 0.f, acc7 = 0.f;

    const uint4* hb = (const uint4*)g_hmT + b * C_ * (HWK / 8);
    const uint4* sPk4 = (const uint4*)sPack;

    #pragma unroll
    for (int cp = 0; cp < 2; cp++) {   // camera pairs {0,1}, {2,3}
        __half2 cam0 = u2h(0u), cam1 = u2h(0u);
        __half2 cam2 = u2h(0u), cam3 = u2h(0u);

        #pragma unroll
        for (int cc = 0; cc < 2; cc++) {
            const int c = cp * 2 + cc;
            const uint4* cb = hb + c * (HWK / 8);
            const uint4 q = sPk4[vloc * 4 + c];  // (idxA, wA, idxB, wB)

            if (q.y | q.w) {
                if (q.y) {
                    const uint4 v = cb[q.x + s8];
                    const __half2 w2 = u2h(__byte_perm(q.y, q.y, sel));
                    cam0 = __hfma2(w2, u2h(v.x), cam0);
                    cam1 = __hfma2(w2, u2h(v.y), cam1);
                    cam2 = __hfma2(w2, u2h(v.z), cam2);
                    cam3 = __hfma2(w2, u2h(v.w), cam3);
                }
                if (q.w) {
                    const uint4 v = cb[q.z + s8];
                    const __half2 w2 = u2h(__byte_perm(q.w, q.w, sel));
                    cam0 = __hfma2(w2, u2h(v.x), cam0);
                    cam1 = __hfma2(w2, u2h(v.y), cam1);
                    cam2 = __hfma2(w2, u2h(v.z), cam2);
                    cam3 = __hfma2(w2, u2h(v.w), cam3);
                }
            }
        }

        float2 f;
        f = __half22float2(cam0); acc0 += f.x; acc1 += f.y;
        f = __half22float2(cam1); acc2 += f.x; acc3 += f.y;
        f = __half22float2(cam2); acc4 += f.x; acc5 += f.y;
        f = __half22float2(cam3); acc6 += f.x; acc7 += f.y;
    }

    // combine the two x-halves (partner lanes s8 and s8^4)
    acc0 += __shfl_xor_sync(0xffffffffu, acc0, 4);
    acc1 += __shfl_xor_sync(0xffffffffu, acc1, 4);
    acc2 += __shfl_xor_sync(0xffffffffu, acc2, 4);
    acc3 += __shfl_xor_sync(0xffffffffu, acc3, 4);
    acc4 += __shfl_xor_sync(0xffffffffu, acc4, 4);
    acc5 += __shfl_xor_sync(0xffffffffu, acc5, 4);
    acc6 += __shfl_xor_sync(0xffffffffu, acc6, 4);
    acc7 += __shfl_xor_sync(0xffffffffu, acc7, 4);

    // stage into smem (lanes s8<4 write; conflict-free)
    if (s8 < 4) {
        float* t = &tile[vloc][8 * s8];
        t[0] = acc0; t[1] = acc1; t[2] = acc2; t[3] = acc3;
        t[4] = acc4; t[5] = acc5; t[6] = acc6; t[7] = acc7;
    }
    __syncthreads();

    // vectorized writeout: one float4 per thread (k, 4-voxel group)
    {
        const int k = tid >> 3;           // 0..31
        const int a = tid & 7;            // group of 4 voxels
        float4 vv;
        vv.x = tile[4 * a + 0][k];
        vv.y = tile[4 * a + 1][k];
        vv.z = tile[4 * a + 2][k];
        vv.w = tile[4 * a + 3][k];
        *(float4*)&out[(b * K_ + k) * NV + nb + 4 * a] = vv;
    }
}

// ---------------------------------------------------------------------------
// Launch
// ---------------------------------------------------------------------------
extern "C" void kernel_launch(void* const* d_in, const int* in_sizes, int n_in,
                              void* d_out, int out_size) {
    const float* heatmaps = (const float*)d_in[0];  // (B,C,K,H,W)
    const float* P        = (const float*)d_in[1];  // (B,C,3,4)
    const float* coords   = (const float*)d_in[2];  // (B,D,D,D,3)
    const float* conf     = (const float*)d_in[3];  // (B,C,K)
    float* out            = (float*)d_out;          // (B,K,D,D,D)

    dim3 tgrid(W_ / 32, H_ / 8, B_ * C_);
    dim3 tblk(32, 32);
    vt_transpose_kernel<<<tgrid, tblk>>>(heatmaps, conf);

    const int nblocks = (B_ * NV) / 32;   // 32 voxels per block
    vt_unproject_kernel<<<nblocks, 256>>>(P, coords, out);
}

// round 16
// speedup vs baseline: 1.2721x; 1.2721x over previous
#include <cuda_runtime.h>
#include <cuda_fp16.h>

// Problem constants (fixed by the reference)
#define B_  2
#define C_  4
#define K_  32
#define H_  96
#define W_  96
#define D_  64
#define NV  (D_*D_*D_)          // 262144 voxels per batch
#define HWK (H_*W_*K_)

// Transposed, confidence-scaled heatmaps in fp16: [b,c,h,w,k] (4.7 MB)
__device__ __half g_hmT[B_ * C_ * HWK];

__device__ __forceinline__ float frcp_approx(float x) {
    float r; asm("rcp.approx.f32 %0, %1;" : "=f"(r) : "f"(x)); return r;
}
__device__ __forceinline__ __half2 u2h(unsigned v) {
    __half2 h; *(unsigned*)&h = v; return h;
}
__device__ __forceinline__ void stcs4(float* p, float4 v) {
    asm volatile("st.global.cs.v4.f32 [%0], {%1, %2, %3, %4};"
                 :: "l"(p), "f"(v.x), "f"(v.y), "f"(v.z), "f"(v.w) : "memory");
}

// ---------------------------------------------------------------------------
// Kernel 1 (measured-best R9): transpose (B,C,K,H,W) -> fp16 (B,C,H,W,K),
// folding normalized conf. grid (W/32, H/8, B*C), block (32,32).
// Stages 8 h-rows, single barrier, coalesced half2 stores.
// ---------------------------------------------------------------------------
__global__ void vt_transpose_kernel(const float* __restrict__ hm,
                                    const float* __restrict__ conf) {
    __shared__ float tile[8][32][33];
    __shared__ float sCn[32];
    const int bc = blockIdx.z;            // b*C + c
    const int b  = bc >> 2;
    const int w0 = blockIdx.x * 32;
    const int h0 = blockIdx.y * 8;
    const int tx = threadIdx.x, ty = threadIdx.y;
    const int tid = ty * 32 + tx;

    if (ty == 0) {
        const int k = tx;
        float s = 0.f;
        #pragma unroll
        for (int cc = 0; cc < C_; cc++) s += conf[(b * C_ + cc) * K_ + k];
        sCn[k] = conf[bc * K_ + k] / s;
    }
    __syncthreads();

    const float cn = sCn[ty];             // k = ty on the read side
    #pragma unroll
    for (int hh = 0; hh < 8; hh++)
        tile[hh][ty][tx] =
            hm[((bc * K_ + ty) * H_ + h0 + hh) * W_ + w0 + tx] * cn;
    __syncthreads();

    __half2* outT = (__half2*)g_hmT;
    #pragma unroll
    for (int i = 0; i < 4; i++) {
        const int idx = tid + i * 1024;
        const int h       = idx >> 9;         // 0..7
        const int w_local = (idx >> 4) & 31;  // 0..31
        const int k2      = idx & 15;         // half2 index 0..15
        outT[(((bc * H_ + h0 + h) * W_ + w0 + w_local) * K_) / 2 + k2] =
            __floats2half2_rn(tile[h][2 * k2 + 0][w_local],
                              tile[h][2 * k2 + 1][w_local]);
    }
}

// ---------------------------------------------------------------------------
// Kernel 2 (measured-best R9 config): two-phase unprojection.
// Block = 128 threads = 32 voxels.
// Phase 1: every thread computes setup for one (voxel, cam) pair; each corner
//          packed into one uint: low16 = row index*4 (uint4 units),
//          high16 = fp16 weight bits (0 if invalid).
// Phase 2: 4 threads/voxel (8 channels each, uint4 = 8 fp16). Bilinear AND
//          camera-pair combine in HFMA2; fp32 convert+add twice per voxel.
// Output stores use st.global.cs (write-once data, evict-first in L2).
// ---------------------------------------------------------------------------
__global__ __launch_bounds__(128, 12) void vt_unproject_kernel(
    const float* __restrict__ P,       // (B,C,3,4)
    const float* __restrict__ coords,  // (B,D,D,D,3)
    float* __restrict__ out)           // (B,K,D,D,D)
{
    const int tid = threadIdx.x;
    const int b   = blockIdx.x >> 13;            // NV/32 = 8192 blocks/batch
    const int nb  = (blockIdx.x & 8191) * 32;    // base voxel within batch

    __shared__ float sP[C_ * 12];
    __shared__ float sCrd[32 * 3];
    __shared__ uint4 sPack[128];       // packed (idx*4 | wh<<16) per corner
    __shared__ float tile[32][33];

    if (tid < C_ * 12) sP[tid] = P[b * C_ * 12 + tid];
    if (tid < 96)      sCrd[tid] = coords[(b * NV + nb) * 3 + tid];
    __syncthreads();

    // ---------------- Phase 1: setup (one (voxel, cam) pair per thread) ----
    {
        const int vox = tid >> 2, cam = tid & 3;
        const float x = sCrd[vox * 3 + 0];
        const float y = sCrd[vox * 3 + 1];
        const float z = sCrd[vox * 3 + 2];
        const float* p = &sP[cam * 12];

        const float pz = fmaf(p[8], x, fmaf(p[9], y, fmaf(p[10], z, p[11])));
        const bool zok = (pz > 0.f);

        const float s  = frcp_approx(pz) * (95.0f / 96.0f);
        const float un = fmaf(p[0], x, fmaf(p[1], y, fmaf(p[2], z, p[3])));
        const float vn = fmaf(p[4], x, fmaf(p[5], y, fmaf(p[6], z, p[7])));
        const float ix = un * s;
        const float iy = vn * s;

        const float x0f = floorf(ix), y0f = floorf(iy);
        const float x1f = x0f + 1.f,  y1f = y0f + 1.f;
        const float wx1 = ix - x0f,   wy1 = iy - y0f;
        const float wx0 = 1.f - wx1,  wy0 = 1.f - wy1;

        const bool bx0 = zok & (x0f >= 0.f) & (x0f <= 95.f);
        const bool bx1 = zok & (x1f >= 0.f) & (x1f <= 95.f);
        const bool by0 = (y0f >= 0.f) & (y0f <= 95.f);
        const bool by1 = (y1f >= 0.f) & (y1f <= 95.f);

        unsigned pk[4];
        #define VT_SETUP(J, BX, BY, XF, YF, WX, WY)                           \
            {                                                                 \
                const bool v = (BX) & (BY);                                   \
                const unsigned raw = (unsigned)(int)fmaf((YF), 96.f, (XF)) * 4u; \
                const float wc = v ? (WX) * (WY) : 0.f;                       \
                const __half hw = __float2half_rn(wc);                        \
                const unsigned whb = (unsigned)*(const unsigned short*)&hw;   \
                pk[J] = (v ? raw : 0u) | (whb << 16);                         \
            }
        VT_SETUP(0, bx0, by0, x0f, y0f, wx0, wy0)
        VT_SETUP(1, bx1, by0, x1f, y0f, wx1, wy0)
        VT_SETUP(2, bx0, by1, x0f, y1f, wx0, wy1)
        VT_SETUP(3, bx1, by1, x1f, y1f, wx1, wy1)
        #undef VT_SETUP

        sPack[tid] = make_uint4(pk[0], pk[1], pk[2], pk[3]);
    }
    __syncthreads();

    // ---------------- Phase 2: wide fp16 gather (4 threads per voxel) ------
    const int g    = tid & 3;          // channel octet (8 halves = 16B)
    const int vloc = tid >> 2;         // voxel within block

    float acc0 = 0.f, acc1 = 0.f, acc2 = 0.f, acc3 = 0.f;
    float acc4 = 0.f, acc5 = 0.f, acc6 = 0.f, acc7 = 0.f;

    // rows are 32 halves = 4 uint4; thread g takes uint4 #g
    const uint4* hb = (const uint4*)g_hmT + b * C_ * (HWK / 8) + g;

    #pragma unroll
    for (int cp = 0; cp < 2; cp++) {   // camera pairs {0,1}, {2,3}
        __half2 cam0 = u2h(0u), cam1 = u2h(0u);
        __half2 cam2 = u2h(0u), cam3 = u2h(0u);

        #pragma unroll
        for (int cc = 0; cc < 2; cc++) {
            const int c = cp * 2 + cc;
            const uint4* cb = hb + c * (HWK / 8);
            const uint4 q = sPack[vloc * 4 + c];

            if ((q.x | q.y | q.z | q.w) > 0xFFFFu) {
                #define VT_CORNER(Q)                                          \
                    if ((Q) > 0xFFFFu) {                                      \
                        const uint4 v = cb[(Q) & 0xFFFFu];                    \
                        const __half2 w2 = u2h(__byte_perm((Q), (Q), 0x3232)); \
                        cam0 = __hfma2(w2, u2h(v.x), cam0);                   \
                        cam1 = __hfma2(w2, u2h(v.y), cam1);                   \
                        cam2 = __hfma2(w2, u2h(v.z), cam2);                   \
                        cam3 = __hfma2(w2, u2h(v.w), cam3);                   \
                    }
                VT_CORNER(q.x)
                VT_CORNER(q.y)
                VT_CORNER(q.z)
                VT_CORNER(q.w)
                #undef VT_CORNER
            }
        }

        float2 f;
        f = __half22float2(cam0); acc0 += f.x; acc1 += f.y;
        f = __half22float2(cam1); acc2 += f.x; acc3 += f.y;
        f = __half22float2(cam2); acc4 += f.x; acc5 += f.y;
        f = __half22float2(cam3); acc6 += f.x; acc7 += f.y;
    }

    // stage into smem (stride-33 scalar stores: conflict-free)
    {
        float* t = &tile[vloc][8 * g];
        t[0] = acc0; t[1] = acc1; t[2] = acc2; t[3] = acc3;
        t[4] = acc4; t[5] = acc5; t[6] = acc6; t[7] = acc7;
    }
    __syncthreads();

    // vectorized writeout: 2 float4 per thread (k, 4-voxel group), streaming
    #pragma unroll
    for (int s = 0; s < 2; s++) {
        const int idx = tid + s * 128;    // 0..255
        const int k = idx >> 3;           // 0..31
        const int a = idx & 7;            // group of 4 voxels
        float4 vv;
        vv.x = tile[4 * a + 0][k];
        vv.y = tile[4 * a + 1][k];
        vv.z = tile[4 * a + 2][k];
        vv.w = tile[4 * a + 3][k];
        stcs4(&out[(b * K_ + k) * NV + nb + 4 * a], vv);
    }
}

// ---------------------------------------------------------------------------
// Launch
// ---------------------------------------------------------------------------
extern "C" void kernel_launch(void* const* d_in, const int* in_sizes, int n_in,
                              void* d_out, int out_size) {
    const float* heatmaps = (const float*)d_in[0];  // (B,C,K,H,W)
    const float* P        = (const float*)d_in[1];  // (B,C,3,4)
    const float* coords   = (const float*)d_in[2];  // (B,D,D,D,3)
    const float* conf     = (const float*)d_in[3];  // (B,C,K)
    float* out            = (float*)d_out;          // (B,K,D,D,D)

    dim3 tgrid(W_ / 32, H_ / 8, B_ * C_);
    dim3 tblk(32, 32);
    vt_transpose_kernel<<<tgrid, tblk>>>(heatmaps, conf);

    const int nblocks = (B_ * NV) / 32;   // 32 voxels per block
    vt_unproject_kernel<<<nblocks, 128>>>(P, coords, out);
}